// round 3
// baseline (speedup 1.0000x reference)
#include <cuda_runtime.h>
#include <cuda_bf16.h>
#include <cstdint>

// Problem constants
#define B_ 64
#define T_ 256
#define H_ 256
#define G4_ 1024      // 4*H
#define K_ 600        // 2*E
#define L_ 15
#define M_ (B_*T_)    // 16384

// ------------------------- device scratch (no allocations) -------------------------
__device__ float d_x[(size_t)M_ * K_];                    // [16384, 600]
__device__ float d_g[(size_t)2 * M_ * G4_];               // [dir][t(or s)][b][1024]
__device__ float d_h[(size_t)M_ * 2 * H_];                // [b][t][512] = [h_f | h_b]
__device__ float d_emis[(size_t)M_ * L_];                 // [b][t][15]
__device__ float d_hbuf[2 * 2 * B_ * H_];                 // [dir][buf][b][256]
__device__ float d_partial[B_];
__device__ unsigned g_cnt[16];                            // per (dir,bbtile) group counters

__device__ __forceinline__ float sigm(float x) {
    float e = __expf(-x);
    return __fdividef(1.0f, 1.0f + e);
}
__device__ __forceinline__ float tanh_ap(float x) {
    float y;
    asm("tanh.approx.f32 %0, %1;" : "=f"(y) : "f"(x));
    return y;
}
__device__ __forceinline__ float sel4(float4 v, int j) {
    float x = v.x;
    x = (j == 1) ? v.y : x;
    x = (j == 2) ? v.z : x;
    x = (j == 3) ? v.w : x;
    return x;
}

// ------------------------- K0: reset barrier counters (per replay) -------------------------
__global__ void k_init() {
    if (threadIdx.x < 16) g_cnt[threadIdx.x] = 0u;
}

// ------------------------- K1: embedding gather + concat -------------------------
// grid = 16384 blocks, 320 threads
__global__ void k_embed(const int* __restrict__ ids, const int* __restrict__ sids,
                        const float* __restrict__ emb, const float* __restrict__ semb) {
    int m = blockIdx.x;
    int c = threadIdx.x;
    if (c >= 300) return;
    int id = ids[m];
    int sid = sids[m];
    d_x[(size_t)m * K_ + c]       = emb[(size_t)id * 300 + c];
    d_x[(size_t)m * K_ + 300 + c] = semb[(size_t)sid * 300 + c];
}

// ------------------------- K2: input GEMM (both directions) -------------------------
// out[dir][row][b][n] = x[m,:] . Wih[n,:] + bih[n] + bhh[n]
// grid = (32 n-tiles of 64, 128 m-tiles of 128), 256 threads, BK=8 (600 = 75*8)
__global__ void __launch_bounds__(256)
k_gemm(const float* __restrict__ Wf, const float* __restrict__ Wb,
       const float* __restrict__ bihf, const float* __restrict__ bhhf,
       const float* __restrict__ bihb, const float* __restrict__ bhhb,
       const int* __restrict__ lengths) {
    __shared__ float As[8][128];
    __shared__ float Bs[8][64];
    int tid = threadIdx.x;
    int n0g = blockIdx.x * 64;
    int dir = n0g >> 10;
    int n0 = n0g & 1023;
    int m0 = blockIdx.y * 128;
    const float* Wp  = dir ? Wb : Wf;
    const float* bih = dir ? bihb : bihf;
    const float* bhh = dir ? bhhb : bhhf;
    int tx = tid & 15, ty = tid >> 4;

    float4 biasv;
    {
        int n = n0 + tx * 4;
        biasv.x = bih[n]     + bhh[n];
        biasv.y = bih[n + 1] + bhh[n + 1];
        biasv.z = bih[n + 2] + bhh[n + 2];
        biasv.w = bih[n + 3] + bhh[n + 3];
    }

    float acc[8][4];
#pragma unroll
    for (int i = 0; i < 8; i++)
#pragma unroll
        for (int j = 0; j < 4; j++) acc[i][j] = 0.f;

    int lr = tid >> 1;            // 0..127
    int lk = (tid & 1) * 4;       // 0 or 4
    const float* xsrc = d_x + (size_t)(m0 + lr) * K_ + lk;
    int brow = tid >> 1;          // for tid<128: 0..63
    const float* wsrc = Wp + (size_t)(n0 + (brow & 63)) * K_ + lk;

    for (int k0 = 0; k0 < K_; k0 += 8) {
        float4 av = *(const float4*)(xsrc + k0);
        As[lk + 0][lr] = av.x;
        As[lk + 1][lr] = av.y;
        As[lk + 2][lr] = av.z;
        As[lk + 3][lr] = av.w;
        if (tid < 128) {
            float4 bv = *(const float4*)(wsrc + k0);
            Bs[lk + 0][brow] = bv.x;
            Bs[lk + 1][brow] = bv.y;
            Bs[lk + 2][brow] = bv.z;
            Bs[lk + 3][brow] = bv.w;
        }
        __syncthreads();
#pragma unroll
        for (int kk = 0; kk < 8; kk++) {
            float4 b4 = *(const float4*)&Bs[kk][tx * 4];
            float4 a0 = *(const float4*)&As[kk][ty * 8];
            float4 a1 = *(const float4*)&As[kk][ty * 8 + 4];
            float a[8] = {a0.x, a0.y, a0.z, a0.w, a1.x, a1.y, a1.z, a1.w};
#pragma unroll
            for (int i = 0; i < 8; i++) {
                acc[i][0] += a[i] * b4.x;
                acc[i][1] += a[i] * b4.y;
                acc[i][2] += a[i] * b4.z;
                acc[i][3] += a[i] * b4.w;
            }
        }
        __syncthreads();
    }

    size_t dirOff = (size_t)dir * M_ * G4_;
#pragma unroll
    for (int i = 0; i < 8; i++) {
        int m = m0 + ty * 8 + i;
        int b = m >> 8, t = m & 255;
        int row = t;
        if (dir) {
            int len = lengths[b];
            row = (t < len) ? (len - 1 - t) : t;
        }
        float4 o;
        o.x = acc[i][0] + biasv.x;
        o.y = acc[i][1] + biasv.y;
        o.z = acc[i][2] + biasv.z;
        o.w = acc[i][3] + biasv.w;
        *(float4*)(d_g + dirOff + ((size_t)row * B_ + b) * G4_ + n0 + tx * 4) = o;
    }
}

// ------------------------- K3: persistent bidirectional LSTM recurrence -------------------------
// grid = 128 blocks (dir 2 x bbtile 8 x unit-tile 8), 256 threads.
// Each block: 8 batches x 32 hidden units; Whh slice (128 rows x 256) in REGISTERS
// (128 floats/thread). h exchanged via L2 (stcg/ldcg), group barrier = 8 blocks.
__global__ void __launch_bounds__(256, 1)
k_rec(const float* __restrict__ Whh_f, const float* __restrict__ Whh_b,
      const int* __restrict__ lengths) {
    __shared__ float sH[8 * 256];        // h_prev for this block's 8 batches
    __shared__ float4 sRed[8 * 8 * 32];  // [kc][bb][rowgroup] partial gate sums

    int tid = threadIdx.x;
    int bx = blockIdx.x;
    int dir = bx >> 6;
    int r6 = bx & 63;
    int bbt = r6 >> 3;
    int ut = r6 & 7;
    int u0 = ut * 32;
    int grp = dir * 8 + bbt;
    const float* Whh = dir ? Whh_b : Whh_f;
    const float* gbase = d_g + (size_t)dir * M_ * G4_;

    // phase-1 mapping: kc = k-chunk (32 wide), rg = 4-row group of the 128 local rows
    int kc = tid >> 5;   // 0..7  (uniform per warp)
    int rg = tid & 31;   // 0..31

    // phase-2 mapping: one (batch, unit) per thread
    int bb2 = tid >> 5;  // 0..7
    int q2 = tid & 31;   // 0..31
    int batch2 = bbt * 8 + bb2;
    int len2 = lengths[batch2];
    int jsel = q2 & 3;

    // load Whh slice into registers: rows rg*4..+3 (local), k in [kc*32, kc*32+32)
    float W[4][32];
#pragma unroll
    for (int j = 0; j < 4; j++) {
        int r = rg * 4 + j;
        int grow = (r >> 5) * 256 + u0 + (r & 31);
        const float* wp = Whh + (size_t)grow * 256 + kc * 32;
#pragma unroll
        for (int kk = 0; kk < 32; kk += 4) {
            float4 v = *(const float4*)(wp + kk);
            W[j][kk] = v.x; W[j][kk + 1] = v.y; W[j][kk + 2] = v.z; W[j][kk + 3] = v.w;
        }
    }

    for (int i = tid; i < 2048; i += 256) sH[i] = 0.f;

    float c = 0.f;
    unsigned target = 0;
    float* hbufDir = d_hbuf + dir * (2 * B_ * H_);
    __syncthreads();

    for (int step = 0; step < 256; step++) {
        // ---- phase 1: gh partials = h_prev . Whh_slice^T ----
        float acc[8][4];
#pragma unroll
        for (int bb = 0; bb < 8; bb++)
#pragma unroll
            for (int j = 0; j < 4; j++) acc[bb][j] = 0.f;

        const float* sB = sH + kc * 32;
#pragma unroll
        for (int kk = 0; kk < 32; kk++) {
            float w0 = W[0][kk], w1 = W[1][kk], w2 = W[2][kk], w3 = W[3][kk];
#pragma unroll
            for (int bb = 0; bb < 8; bb++) {
                float hv = sB[bb * 256 + kk];   // warp-broadcast, conflict-free
                acc[bb][0] += hv * w0;
                acc[bb][1] += hv * w1;
                acc[bb][2] += hv * w2;
                acc[bb][3] += hv * w3;
            }
        }
#pragma unroll
        for (int bb = 0; bb < 8; bb++)
            sRed[(kc * 8 + bb) * 32 + rg] =
                make_float4(acc[bb][0], acc[bb][1], acc[bb][2], acc[bb][3]);
        __syncthreads();

        // ---- phase 2: gates, cell update, h out ----
        const float* gx = gbase + ((size_t)step * B_ + batch2) * G4_;
        float gate[4];
#pragma unroll
        for (int g = 0; g < 4; g++) {
            int rgl = g * 8 + (q2 >> 2);        // (g*32+q2) >> 2
            float s = gx[g * 256 + u0 + q2];
#pragma unroll
            for (int kcc = 0; kcc < 8; kcc++)
                s += sel4(sRed[(kcc * 8 + bb2) * 32 + rgl], jsel);
            gate[g] = s;
        }
        float i_ = sigm(gate[0]);
        float f_ = sigm(gate[1]);
        float gg = tanh_ap(gate[2]);
        float o_ = sigm(gate[3]);
        c = f_ * c + i_ * gg;
        float h = o_ * tanh_ap(c);

        int wbuf = step & 1;
        __stcg(&hbufDir[(wbuf * B_ + batch2) * H_ + u0 + q2], h);
        int tout = dir ? ((step < len2) ? (len2 - 1 - step) : step) : step;
        d_h[((size_t)batch2 * T_ + tout) * 512 + dir * 256 + u0 + q2] = h;

        // ---- group barrier (8 blocks sharing this batch tile) ----
        __threadfence();
        __syncthreads();
        target += 8;
        if (tid == 0) {
            atomicAdd(&g_cnt[grp], 1u);
            while (*(volatile unsigned*)&g_cnt[grp] < target) { }
            __threadfence();
        }
        __syncthreads();

        // ---- reload full h_prev for next step (L2-coherent loads) ----
        const float4* src = (const float4*)(hbufDir + (wbuf * B_ + bbt * 8) * H_);
        for (int i = tid; i < 512; i += 256)
            ((float4*)sH)[i] = __ldcg(src + i);
        __syncthreads();
    }
}

// ------------------------- K4: emissions = h . Wlin^T + blin -------------------------
// grid = 2048 blocks (8 rows each), 128 threads (8 rows x 16 label-slots)
__global__ void __launch_bounds__(128)
k_emis(const float* __restrict__ Wlin, const float* __restrict__ blin) {
    __shared__ float sW[15 * 516];
    __shared__ float sh[8 * 512];
    int tid = threadIdx.x;
    for (int i = tid; i < 15 * 512; i += 128) {
        int l = i >> 9, k = i & 511;
        sW[l * 516 + k] = Wlin[i];
    }
    int m0 = blockIdx.x * 8;
    const float4* hsrc = (const float4*)(d_h + (size_t)m0 * 512);
    for (int i = tid; i < 8 * 512 / 4; i += 128)
        ((float4*)sh)[i] = hsrc[i];
    __syncthreads();

    int r = tid >> 4, l = tid & 15;
    if (l < 15) {
        float s = blin[l];
        const float* hw = sh + r * 512;
        const float* ww = sW + l * 516;
#pragma unroll 8
        for (int k = 0; k < 512; k += 4) {
            float4 hv = *(const float4*)(hw + k);
            float4 wv = *(const float4*)(ww + k);
            s += hv.x * wv.x + hv.y * wv.y + hv.z * wv.z + hv.w * wv.w;
        }
        d_emis[(size_t)(m0 + r) * L_ + l] = s;
    }
}

// ------------------------- K5: CRF NLL per sequence -------------------------
// grid = 64 blocks, 32 threads (one warp per sequence; lanes 0..14 hold alpha)
__global__ void k_crf(const int* __restrict__ lengths, const int* __restrict__ labels,
                      const float* __restrict__ start_t, const float* __restrict__ end_t,
                      const float* __restrict__ trans) {
    int b = blockIdx.x;
    int lane = threadIdx.x;
    int len = lengths[b];
    const float* em = d_emis + (size_t)b * T_ * L_;
    int j = (lane < L_) ? lane : 0;

    float tr[L_];
#pragma unroll
    for (int i = 0; i < L_; i++) tr[i] = trans[i * L_ + j];

    float alpha = start_t[j] + em[j];
    for (int t = 1; t < T_; t++) {
        float v[L_], mx = -1e30f;
#pragma unroll
        for (int i = 0; i < L_; i++) {
            float av = __shfl_sync(0xffffffffu, alpha, i);
            v[i] = av + tr[i];
            mx = fmaxf(mx, v[i]);
        }
        float s = 0.f;
#pragma unroll
        for (int i = 0; i < L_; i++) s += __expf(v[i] - mx);
        float nxt = mx + __logf(s) + em[t * L_ + j];
        if (t < len) alpha = nxt;
    }
    // log-partition
    float vv = (lane < L_) ? (alpha + end_t[lane]) : -1e30f;
    float mx = vv;
#pragma unroll
    for (int o = 16; o; o >>= 1) mx = fmaxf(mx, __shfl_xor_sync(0xffffffffu, mx, o));
    float se = (lane < L_) ? __expf(vv - mx) : 0.f;
#pragma unroll
    for (int o = 16; o; o >>= 1) se += __shfl_xor_sync(0xffffffffu, se, o);
    float den = mx + __logf(se);

    // gold-path score
    const int* tg = labels + b * T_;
    float em_s = 0.f, tr_s = 0.f;
    for (int t = lane; t < T_; t += 32) {
        if (t < len) {
            em_s += em[t * L_ + tg[t]];
            if (t >= 1) tr_s += trans[tg[t - 1] * L_ + tg[t]];
        }
    }
#pragma unroll
    for (int o = 16; o; o >>= 1) {
        em_s += __shfl_xor_sync(0xffffffffu, em_s, o);
        tr_s += __shfl_xor_sync(0xffffffffu, tr_s, o);
    }
    if (lane == 0) {
        float num = start_t[tg[0]] + em_s + tr_s + end_t[tg[len - 1]];
        d_partial[b] = num - den;
    }
}

// ------------------------- K6: deterministic final sum -------------------------
__global__ void k_final(float* __restrict__ out) {
    float s = 0.f;
#pragma unroll
    for (int b = 0; b < B_; b++) s += d_partial[b];
    out[0] = -s;
}

// ------------------------- launch -------------------------
extern "C" void kernel_launch(void* const* d_in, const int* in_sizes, int n_in,
                              void* d_out, int out_size) {
    const int*   input_ids    = (const int*)d_in[0];
    const int*   lengths      = (const int*)d_in[1];
    const int*   softword_ids = (const int*)d_in[2];
    const int*   label_ids    = (const int*)d_in[3];
    const float* emb          = (const float*)d_in[4];
    const float* soft_emb     = (const float*)d_in[5];
    const float* Wih_f        = (const float*)d_in[6];
    const float* Whh_f        = (const float*)d_in[7];
    const float* bih_f        = (const float*)d_in[8];
    const float* bhh_f        = (const float*)d_in[9];
    const float* Wih_b        = (const float*)d_in[10];
    const float* Whh_b        = (const float*)d_in[11];
    const float* bih_b        = (const float*)d_in[12];
    const float* bhh_b        = (const float*)d_in[13];
    const float* Wlin         = (const float*)d_in[14];
    const float* blin         = (const float*)d_in[15];
    const float* start_t      = (const float*)d_in[16];
    const float* end_t        = (const float*)d_in[17];
    const float* trans        = (const float*)d_in[18];
    float* out = (float*)d_out;

    k_init<<<1, 32>>>();
    k_embed<<<M_, 320>>>(input_ids, softword_ids, emb, soft_emb);
    dim3 g2(32, 128);
    k_gemm<<<g2, 256>>>(Wih_f, Wih_b, bih_f, bhh_f, bih_b, bhh_b, lengths);
    k_rec<<<128, 256>>>(Whh_f, Whh_b, lengths);
    k_emis<<<2048, 128>>>(Wlin, blin);
    k_crf<<<B_, 32>>>(lengths, label_ids, start_t, end_t, trans);
    k_final<<<1, 1>>>(out);
}

// round 5
// speedup vs baseline: 1.4697x; 1.4697x over previous
#include <cuda_runtime.h>
#include <cuda_bf16.h>
#include <cstdint>

// Problem constants
#define B_ 64
#define T_ 256
#define H_ 256
#define G4_ 1024      // 4*H
#define KRAW 600      // 2*E
#define KP 640        // padded K (20 chunks of 32)
#define L_ 15
#define M_ (B_*T_)    // 16384

// ------------------------- device scratch (no allocations) -------------------------
__device__ __align__(16) __nv_bfloat16 d_xb[(size_t)M_ * KP];    // [16384, 640] bf16
__device__ __align__(16) __nv_bfloat16 d_wb[(size_t)2048 * KP];  // [2048, 640] bf16 (fwd 0..1023, bwd 1024..2047)
__device__ float d_g[(size_t)2 * M_ * G4_];               // [dir][t(or s)][b][1024]
__device__ float d_h[(size_t)M_ * 2 * H_];                // [b][t][512] = [h_f | h_b]
__device__ float d_emis[(size_t)M_ * L_];                 // [b][t][15]
__device__ float d_hbuf[2 * 2 * B_ * H_];                 // [dir][buf][b][256]
__device__ float d_partial[B_];
__device__ unsigned g_cnt[16];

// ------------------------- helpers -------------------------
__device__ __forceinline__ float sigm(float x) {
    float e = __expf(-x);
    return __fdividef(1.0f, 1.0f + e);
}
__device__ __forceinline__ float tanh_ap(float x) {
    float y;
    asm("tanh.approx.f32 %0, %1;" : "=f"(y) : "f"(x));
    return y;
}
__device__ __forceinline__ float sel4(float4 v, int j) {
    float x = v.x;
    x = (j == 1) ? v.y : x;
    x = (j == 2) ? v.z : x;
    x = (j == 3) ? v.w : x;
    return x;
}
__device__ __forceinline__ uint32_t smem_u32(const void* p) {
    uint32_t a;
    asm("{ .reg .u64 t; cvta.to.shared.u64 t, %1; cvt.u32.u64 %0, t; }" : "=r"(a) : "l"(p));
    return a;
}

// ------------------------- K0: reset barrier counters -------------------------
__global__ void k_init() {
    if (threadIdx.x < 16) g_cnt[threadIdx.x] = 0u;
}

// ------------------------- K1: embedding gather + concat + bf16 + pad -------------------------
__global__ void k_embed(const int* __restrict__ ids, const int* __restrict__ sids,
                        const float* __restrict__ emb, const float* __restrict__ semb) {
    int m = blockIdx.x;
    int c = threadIdx.x;
    __nv_bfloat16* xp = d_xb + (size_t)m * KP;
    if (c < 300) {
        int id = ids[m];
        int sid = sids[m];
        xp[c]       = __float2bfloat16_rn(emb[(size_t)id * 300 + c]);
        xp[300 + c] = __float2bfloat16_rn(semb[(size_t)sid * 300 + c]);
    } else {
        int z = c - 300;
        xp[600 + z] = __float2bfloat16_rn(0.f);
        xp[620 + z] = __float2bfloat16_rn(0.f);
    }
}

// ------------------------- K1b: weight conversion to bf16 (padded) -------------------------
__global__ void k_wconv(const float* __restrict__ Wf, const float* __restrict__ Wb) {
    int idx = blockIdx.x * blockDim.x + threadIdx.x;
    if (idx >= 2048 * KP) return;
    int row = idx / KP, k = idx - row * KP;
    float v = 0.f;
    if (k < KRAW) v = (row < 1024) ? Wf[row * KRAW + k] : Wb[(row - 1024) * KRAW + k];
    d_wb[idx] = __float2bfloat16_rn(v);
}

// ------------------------- K2: mma.sync bf16 GEMM -------------------------
// C[16384, 2048] = Xb . Wb^T, CTA tile 128x128, warp tile 32x64, K-chunk 32 (x20), double-buffered.
// grid = (16 n-tiles, 128 m-tiles), 256 threads.
#define APITCH 40   // 32 + 8 pad (80B pitch: 16B-aligned, ldmatrix conflict-free)

__device__ __forceinline__ void ldm_x4(uint32_t* r, uint32_t addr) {
    asm volatile("ldmatrix.sync.aligned.m8n8.x4.shared.b16 {%0,%1,%2,%3}, [%4];"
                 : "=r"(r[0]), "=r"(r[1]), "=r"(r[2]), "=r"(r[3]) : "r"(addr));
}
__device__ __forceinline__ void mma16816(float* c, const uint32_t* a, const uint32_t* b) {
    asm volatile(
        "mma.sync.aligned.m16n8k16.row.col.f32.bf16.bf16.f32 "
        "{%0,%1,%2,%3}, {%4,%5,%6,%7}, {%8,%9}, {%0,%1,%2,%3};"
        : "+f"(c[0]), "+f"(c[1]), "+f"(c[2]), "+f"(c[3])
        : "r"(a[0]), "r"(a[1]), "r"(a[2]), "r"(a[3]), "r"(b[0]), "r"(b[1]));
}

__global__ void __launch_bounds__(256, 1)
k_gemm_mma(const float* __restrict__ bihf, const float* __restrict__ bhhf,
           const float* __restrict__ bihb, const float* __restrict__ bhhb,
           const int* __restrict__ lengths) {
    __shared__ __align__(16) __nv_bfloat16 sA[2][128][APITCH];
    __shared__ __align__(16) __nv_bfloat16 sB[2][128][APITCH];

    int tid = threadIdx.x;
    int wid = tid >> 5;
    int lane = tid & 31;
    int warpM = wid & 3;       // 4 m-warps
    int warpN = wid >> 2;      // 2 n-warps
    int m0 = blockIdx.y * 128;
    int n0g = blockIdx.x * 128;        // 0..1920 over 2048
    int dir = n0g >> 10;
    int n0 = n0g & 1023;

    const __nv_bfloat16* xa = d_xb + (size_t)m0 * KP;
    const __nv_bfloat16* wa = d_wb + (size_t)n0g * KP;

    // load indices: 512 uint4 per tile, 2 per thread
    int v0 = tid * 2;
    int r0i = v0 >> 2, j0 = v0 & 3;
    int v1 = v0 + 1;
    int r1i = v1 >> 2, j1 = v1 & 3;

    float acc[2][8][4];
#pragma unroll
    for (int mf = 0; mf < 2; mf++)
#pragma unroll
        for (int nf = 0; nf < 8; nf++)
#pragma unroll
            for (int q = 0; q < 4; q++) acc[mf][nf][q] = 0.f;

    // prologue: chunk 0 -> buf 0
    {
        uint4 a0 = *(const uint4*)(xa + (size_t)r0i * KP + j0 * 8);
        uint4 a1 = *(const uint4*)(xa + (size_t)r1i * KP + j1 * 8);
        uint4 b0 = *(const uint4*)(wa + (size_t)r0i * KP + j0 * 8);
        uint4 b1 = *(const uint4*)(wa + (size_t)r1i * KP + j1 * 8);
        *(uint4*)&sA[0][r0i][j0 * 8] = a0;
        *(uint4*)&sA[0][r1i][j1 * 8] = a1;
        *(uint4*)&sB[0][r0i][j0 * 8] = b0;
        *(uint4*)&sB[0][r1i][j1 * 8] = b1;
    }
    __syncthreads();

    // ldmatrix lane addressing
    int aRow = warpM * 32 + (lane & 15);
    int aCol = (lane >> 4) << 3;              // 0 or 8
    int bRowBase = warpN * 64 + ((lane >> 4) << 3) + (lane & 7);
    int bCol = ((lane >> 3) & 1) << 3;        // 0 or 8

    for (int c = 0; c < 20; c++) {
        int buf = c & 1;
        uint4 na0, na1, nb0, nb1;
        if (c + 1 < 20) {
            const __nv_bfloat16* xan = xa + (c + 1) * 32;
            const __nv_bfloat16* wan = wa + (c + 1) * 32;
            na0 = *(const uint4*)(xan + (size_t)r0i * KP + j0 * 8);
            na1 = *(const uint4*)(xan + (size_t)r1i * KP + j1 * 8);
            nb0 = *(const uint4*)(wan + (size_t)r0i * KP + j0 * 8);
            nb1 = *(const uint4*)(wan + (size_t)r1i * KP + j1 * 8);
        }
#pragma unroll
        for (int ks = 0; ks < 2; ks++) {
            int kc = ks * 16;
            uint32_t af[2][4];
#pragma unroll
            for (int mf = 0; mf < 2; mf++)
                ldm_x4(af[mf], smem_u32(&sA[buf][aRow + mf * 16][kc + aCol]));
            uint32_t bf[4][4];
#pragma unroll
            for (int p = 0; p < 4; p++)
                ldm_x4(bf[p], smem_u32(&sB[buf][bRowBase + p * 16][kc + bCol]));
#pragma unroll
            for (int mf = 0; mf < 2; mf++)
#pragma unroll
                for (int nf = 0; nf < 8; nf++)
                    mma16816(acc[mf][nf], af[mf], &bf[nf >> 1][(nf & 1) * 2]);
        }
        if (c + 1 < 20) {
            int nb = (c + 1) & 1;
            *(uint4*)&sA[nb][r0i][j0 * 8] = na0;
            *(uint4*)&sA[nb][r1i][j1 * 8] = na1;
            *(uint4*)&sB[nb][r0i][j0 * 8] = nb0;
            *(uint4*)&sB[nb][r1i][j1 * 8] = nb1;
            __syncthreads();
        }
    }

    // epilogue: direct stores with bias + time reversal
    const float* bihp = dir ? bihb : bihf;
    const float* bhhp = dir ? bhhb : bhhf;
    int groupID = lane >> 2;
    int qn = (lane & 3) * 2;
#pragma unroll
    for (int mf = 0; mf < 2; mf++) {
#pragma unroll
        for (int mr = 0; mr < 2; mr++) {
            int m = m0 + warpM * 32 + mf * 16 + groupID + mr * 8;
            int b = m >> 8, t = m & 255;
            int row = t;
            if (dir) {
                int len = lengths[b];
                row = (t < len) ? (len - 1 - t) : t;
            }
            float* outp = d_g + ((size_t)dir * M_ + (size_t)row * B_ + b) * G4_;
#pragma unroll
            for (int nf = 0; nf < 8; nf++) {
                int n = n0 + warpN * 64 + nf * 8 + qn;
                float2 o;
                o.x = acc[mf][nf][mr * 2 + 0] + bihp[n] + bhhp[n];
                o.y = acc[mf][nf][mr * 2 + 1] + bihp[n + 1] + bhhp[n + 1];
                *(float2*)(outp + n) = o;
            }
        }
    }
}

// ------------------------- K3: persistent bidirectional LSTM recurrence -------------------------
__global__ void __launch_bounds__(256, 1)
k_rec(const float* __restrict__ Whh_f, const float* __restrict__ Whh_b,
      const int* __restrict__ lengths) {
    __shared__ float sH[8 * 256];
    __shared__ float4 sRed[8 * 8 * 32];

    int tid = threadIdx.x;
    int bx = blockIdx.x;
    int dir = bx >> 6;
    int r6 = bx & 63;
    int bbt = r6 >> 3;
    int ut = r6 & 7;
    int u0 = ut * 32;
    int grp = dir * 8 + bbt;
    const float* Whh = dir ? Whh_b : Whh_f;
    const float* gbase = d_g + (size_t)dir * M_ * G4_;

    int kc = tid >> 5;
    int rg = tid & 31;

    int bb2 = tid >> 5;
    int q2 = tid & 31;
    int batch2 = bbt * 8 + bb2;
    int len2 = lengths[batch2];
    int jsel = q2 & 3;

    float W[4][32];
#pragma unroll
    for (int j = 0; j < 4; j++) {
        int r = rg * 4 + j;
        int grow = (r >> 5) * 256 + u0 + (r & 31);
        const float* wp = Whh + (size_t)grow * 256 + kc * 32;
#pragma unroll
        for (int kk = 0; kk < 32; kk += 4) {
            float4 v = *(const float4*)(wp + kk);
            W[j][kk] = v.x; W[j][kk + 1] = v.y; W[j][kk + 2] = v.z; W[j][kk + 3] = v.w;
        }
    }

    for (int i = tid; i < 2048; i += 256) sH[i] = 0.f;

    float c = 0.f;
    unsigned target = 0;
    float* hbufDir = d_hbuf + dir * (2 * B_ * H_);
    __syncthreads();

    for (int step = 0; step < 256; step++) {
        const float* gx = gbase + ((size_t)step * B_ + batch2) * G4_;
        float gpre[4];
#pragma unroll
        for (int g = 0; g < 4; g++) gpre[g] = gx[g * 256 + u0 + q2];

        float acc[8][4];
#pragma unroll
        for (int bb = 0; bb < 8; bb++)
#pragma unroll
            for (int j = 0; j < 4; j++) acc[bb][j] = 0.f;

        const float* sB2 = sH + kc * 32;
#pragma unroll
        for (int kk = 0; kk < 32; kk++) {
            float w0 = W[0][kk], w1 = W[1][kk], w2 = W[2][kk], w3 = W[3][kk];
#pragma unroll
            for (int bb = 0; bb < 8; bb++) {
                float hv = sB2[bb * 256 + kk];
                acc[bb][0] += hv * w0;
                acc[bb][1] += hv * w1;
                acc[bb][2] += hv * w2;
                acc[bb][3] += hv * w3;
            }
        }
#pragma unroll
        for (int bb = 0; bb < 8; bb++)
            sRed[(kc * 8 + bb) * 32 + rg] =
                make_float4(acc[bb][0], acc[bb][1], acc[bb][2], acc[bb][3]);
        __syncthreads();

        float gate[4];
#pragma unroll
        for (int g = 0; g < 4; g++) {
            int rgl = g * 8 + (q2 >> 2);
            float s = gpre[g];
#pragma unroll
            for (int kcc = 0; kcc < 8; kcc++)
                s += sel4(sRed[(kcc * 8 + bb2) * 32 + rgl], jsel);
            gate[g] = s;
        }
        float i_ = sigm(gate[0]);
        float f_ = sigm(gate[1]);
        float gg = tanh_ap(gate[2]);
        float o_ = sigm(gate[3]);
        c = f_ * c + i_ * gg;
        float h = o_ * tanh_ap(c);

        int wbuf = step & 1;
        __stcg(&hbufDir[(wbuf * B_ + batch2) * H_ + u0 + q2], h);
        int tout = dir ? ((step < len2) ? (len2 - 1 - step) : step) : step;
        d_h[((size_t)batch2 * T_ + tout) * 512 + dir * 256 + u0 + q2] = h;

        __threadfence();
        __syncthreads();
        target += 8;
        if (tid == 0) {
            atomicAdd(&g_cnt[grp], 1u);
            while (*(volatile unsigned*)&g_cnt[grp] < target) { }
            __threadfence();
        }
        __syncthreads();

        const float4* src = (const float4*)(hbufDir + (wbuf * B_ + bbt * 8) * H_);
        for (int i = tid; i < 512; i += 256)
            ((float4*)sH)[i] = __ldcg(src + i);
        __syncthreads();
    }
}

// ------------------------- K4: emissions = h . Wlin^T + blin -------------------------
__global__ void __launch_bounds__(128)
k_emis(const float* __restrict__ Wlin, const float* __restrict__ blin) {
    __shared__ float sW[15 * 516];
    __shared__ float sh[8 * 512];
    int tid = threadIdx.x;
    for (int i = tid; i < 15 * 512; i += 128) {
        int l = i >> 9, k = i & 511;
        sW[l * 516 + k] = Wlin[i];
    }
    int m0 = blockIdx.x * 8;
    const float4* hsrc = (const float4*)(d_h + (size_t)m0 * 512);
    for (int i = tid; i < 8 * 512 / 4; i += 128)
        ((float4*)sh)[i] = hsrc[i];
    __syncthreads();

    int r = tid >> 4, l = tid & 15;
    if (l < 15) {
        float s = blin[l];
        const float* hw = sh + r * 512;
        const float* ww = sW + l * 516;
#pragma unroll 8
        for (int k = 0; k < 512; k += 4) {
            float4 hv = *(const float4*)(hw + k);
            float4 wv = *(const float4*)(ww + k);
            s += hv.x * wv.x + hv.y * wv.y + hv.z * wv.z + hv.w * wv.w;
        }
        d_emis[(size_t)(m0 + r) * L_ + l] = s;
    }
}

// ------------------------- K5: CRF NLL per sequence -------------------------
__global__ void k_crf(const int* __restrict__ lengths, const int* __restrict__ labels,
                      const float* __restrict__ start_t, const float* __restrict__ end_t,
                      const float* __restrict__ trans) {
    int b = blockIdx.x;
    int lane = threadIdx.x;
    int len = lengths[b];
    const float* em = d_emis + (size_t)b * T_ * L_;
    int j = (lane < L_) ? lane : 0;

    float tr[L_];
#pragma unroll
    for (int i = 0; i < L_; i++) tr[i] = trans[i * L_ + j];

    float alpha = start_t[j] + em[j];
    for (int t = 1; t < T_; t++) {
        float v[L_], mx = -1e30f;
#pragma unroll
        for (int i = 0; i < L_; i++) {
            float av = __shfl_sync(0xffffffffu, alpha, i);
            v[i] = av + tr[i];
            mx = fmaxf(mx, v[i]);
        }
        float s = 0.f;
#pragma unroll
        for (int i = 0; i < L_; i++) s += __expf(v[i] - mx);
        float nxt = mx + __logf(s) + em[t * L_ + j];
        if (t < len) alpha = nxt;
    }
    float vv = (lane < L_) ? (alpha + end_t[lane]) : -1e30f;
    float mx = vv;
#pragma unroll
    for (int o = 16; o; o >>= 1) mx = fmaxf(mx, __shfl_xor_sync(0xffffffffu, mx, o));
    float se = (lane < L_) ? __expf(vv - mx) : 0.f;
#pragma unroll
    for (int o = 16; o; o >>= 1) se += __shfl_xor_sync(0xffffffffu, se, o);
    float den = mx + __logf(se);

    const int* tg = labels + b * T_;
    float em_s = 0.f, tr_s = 0.f;
    for (int t = lane; t < T_; t += 32) {
        if (t < len) {
            em_s += em[t * L_ + tg[t]];
            if (t >= 1) tr_s += trans[tg[t - 1] * L_ + tg[t]];
        }
    }
#pragma unroll
    for (int o = 16; o; o >>= 1) {
        em_s += __shfl_xor_sync(0xffffffffu, em_s, o);
        tr_s += __shfl_xor_sync(0xffffffffu, tr_s, o);
    }
    if (lane == 0) {
        float num = start_t[tg[0]] + em_s + tr_s + end_t[tg[len - 1]];
        d_partial[b] = num - den;
    }
}

// ------------------------- K6: deterministic final sum -------------------------
__global__ void k_final(float* __restrict__ out) {
    float s = 0.f;
#pragma unroll
    for (int b = 0; b < B_; b++) s += d_partial[b];
    out[0] = -s;
}

// ------------------------- launch -------------------------
extern "C" void kernel_launch(void* const* d_in, const int* in_sizes, int n_in,
                              void* d_out, int out_size) {
    const int*   input_ids    = (const int*)d_in[0];
    const int*   lengths      = (const int*)d_in[1];
    const int*   softword_ids = (const int*)d_in[2];
    const int*   label_ids    = (const int*)d_in[3];
    const float* emb          = (const float*)d_in[4];
    const float* soft_emb     = (const float*)d_in[5];
    const float* Wih_f        = (const float*)d_in[6];
    const float* Whh_f        = (const float*)d_in[7];
    const float* bih_f        = (const float*)d_in[8];
    const float* bhh_f        = (const float*)d_in[9];
    const float* Wih_b        = (const float*)d_in[10];
    const float* Whh_b        = (const float*)d_in[11];
    const float* bih_b        = (const float*)d_in[12];
    const float* bhh_b        = (const float*)d_in[13];
    const float* Wlin         = (const float*)d_in[14];
    const float* blin         = (const float*)d_in[15];
    const float* start_t      = (const float*)d_in[16];
    const float* end_t        = (const float*)d_in[17];
    const float* trans        = (const float*)d_in[18];
    float* out = (float*)d_out;

    k_init<<<1, 32>>>();
    k_embed<<<M_, 320>>>(input_ids, softword_ids, emb, soft_emb);
    k_wconv<<<(2048 * KP + 511) / 512, 512>>>(Wih_f, Wih_b);
    dim3 g2(16, 128);
    k_gemm_mma<<<g2, 256>>>(bih_f, bhh_f, bih_b, bhh_b, lengths);
    k_rec<<<128, 256>>>(Whh_f, Whh_b, lengths);
    k_emis<<<2048, 128>>>(Wlin, blin);
    k_crf<<<B_, 32>>>(lengths, label_ids, start_t, end_t, trans);
    k_final<<<1, 1>>>(out);
}